// round 14
// baseline (speedup 1.0000x reference)
#include <cuda_runtime.h>
#include <cstdint>

#define BB 8
#define NN 2048
#define DD 128
#define K_TOP 8
#define TILE 128
#define NT 16
#define PADC 132
#define NEG_INF (-3.402823466e38f)

#define KC 16
#define NCH 8
#define PADM 132
#define AST_F (KC * PADM)     // 2112 floats per staged tile

// smem word offsets (floats)
#define CS_F   (TILE * PADC)          // 16896
#define SGV_O  CS_F
#define SGI_O  (CS_F + 7 * 256)
#define SEI_O  (CS_F + 14 * 256)
#define SM_TOT (CS_F + 22 * 256)      // 22528 words = 90112 B

__device__ float g_normed[BB * NN * DD];
__device__ float g_pval[BB * NN * NT * K_TOP];
__device__ int   g_pidx[BB * NN * NT * K_TOP];

#define FMA2(d, a, b) asm("fma.rn.f32x2 %0, %1, %2, %0;" : "+l"(d) : "l"(a), "l"(b))
__device__ __forceinline__ unsigned long long pk2(float lo, float hi) {
    unsigned long long d;
    asm("mov.b64 %0, {%1, %2};" : "=l"(d) : "f"(lo), "f"(hi));
    return d;
}
__device__ __forceinline__ void upk2(float& lo, float& hi, unsigned long long v) {
    asm("mov.b64 {%0, %1}, %2;" : "=f"(lo), "=f"(hi) : "l"(v));
}
#define CASF(a, b) { float _t = fminf(a, b); b = fmaxf(a, b); a = _t; }

// sort 8 ascending (Batcher, 19 CAS) then merge into running sorted s[8]
#define SORT8_MERGE(e, s)                                                   \
    CASF(e[0], e[1]) CASF(e[2], e[3]) CASF(e[4], e[5]) CASF(e[6], e[7])     \
    CASF(e[0], e[2]) CASF(e[1], e[3]) CASF(e[4], e[6]) CASF(e[5], e[7])     \
    CASF(e[1], e[2]) CASF(e[5], e[6])                                       \
    CASF(e[0], e[4]) CASF(e[1], e[5]) CASF(e[2], e[6]) CASF(e[3], e[7])     \
    CASF(e[2], e[4]) CASF(e[3], e[5])                                       \
    CASF(e[1], e[2]) CASF(e[3], e[4]) CASF(e[5], e[6])                      \
    _Pragma("unroll")                                                       \
    for (int _i = 0; _i < 8; _i++) s[_i] = fmaxf(s[_i], e[7 - _i]);         \
    CASF(s[0], s[4]) CASF(s[1], s[5]) CASF(s[2], s[6]) CASF(s[3], s[7])     \
    CASF(s[0], s[2]) CASF(s[1], s[3]) CASF(s[4], s[6]) CASF(s[5], s[7])     \
    CASF(s[0], s[1]) CASF(s[2], s[3]) CASF(s[4], s[5]) CASF(s[6], s[7])

// ---------------------------------------------------------------------------
__global__ void dummy_kernel() {}   // keeps gemm in ncu's profiled slot

// normalize rows (one warp each) + zero the output (grid-stride)
__global__ void normzero_kernel(const float* __restrict__ x,
                                float4* __restrict__ out, int n4) {
    int row  = (blockIdx.x * blockDim.x + threadIdx.x) >> 5;
    int lane = threadIdx.x & 31;
    {
        float4 v = ((const float4*)(x + (size_t)row * DD))[lane];
        float s = v.x * v.x + v.y * v.y + v.z * v.z + v.w * v.w;
        #pragma unroll
        for (int o = 16; o; o >>= 1) s += __shfl_xor_sync(0xffffffffu, s, o);
        float nrm = fmaxf(sqrtf(s), 1e-12f);
        float4 ov = make_float4(v.x / nrm, v.y / nrm, v.z / nrm, v.w / nrm);
        ((float4*)(g_normed + (size_t)row * DD))[lane] = ov;
    }
    float4 z = make_float4(0.f, 0.f, 0.f, 0.f);
    for (int i = blockIdx.x * blockDim.x + threadIdx.x; i < n4; i += 2048 * 256)
        out[i] = z;
}

// ---------------------------------------------------------------------------
// two-pass exact top-8 for the gemm tile scan
// ---------------------------------------------------------------------------
__device__ __forceinline__ void scan_topk2(const float* __restrict__ base, int stp,
                                           int ib, int tid, float* sm,
                                           float* __restrict__ pv, int* __restrict__ pi) {
    float s[8];
    #pragma unroll
    for (int k = 0; k < 8; k++) s[k] = NEG_INF;

    for (int g = 0; g < 16; g++) {
        float e[8];
        if (stp == 1) {
            float4 v0 = *(const float4*)&base[8 * g];
            float4 v1 = *(const float4*)&base[8 * g + 4];
            e[0] = v0.x; e[1] = v0.y; e[2] = v0.z; e[3] = v0.w;
            e[4] = v1.x; e[5] = v1.y; e[6] = v1.z; e[7] = v1.w;
        } else {
            #pragma unroll
            for (int j = 0; j < 8; j++) e[j] = base[(8 * g + j) * stp];
        }
        SORT8_MERGE(e, s)
    }
    float V8 = s[0];   // exact 8th-largest of the 128

    float* sgv = sm + SGV_O;
    int*   sgi = (int*)(sm + SGI_O);
    int*   sei = (int*)(sm + SEI_O);
    int gc = 0, ec = 0;
    for (int k = 0; k < TILE; k++) {
        float v = base[k * stp];
        if (v > V8) {
            sgv[gc * 256 + tid] = v;
            sgi[gc * 256 + tid] = ib + k;
            gc++;
        } else if (v == V8 && ec < 8) {
            sei[ec * 256 + tid] = ib + k;
            ec++;
        }
    }
    #pragma unroll
    for (int q = 0; q < 8; q++) {
        bool g = q < gc;
        int ei = q - gc; if (ei < 0) ei = 0;
        pv[q] = g ? sgv[q * 256 + tid] : V8;
        pi[q] = g ? sgi[q * 256 + tid] : sei[ei * 256 + tid];
    }
}

// ---------------------------------------------------------------------------
// symmetric 128x128 tile: R9 f32x2 GEMM core + network two-pass top-8
// grid (136, 8), 256 threads, 2 CTAs/SM, dyn smem = 90112 B
// ---------------------------------------------------------------------------
__global__ void __launch_bounds__(256, 2) gemm_topk_kernel() {
    extern __shared__ float sm[];
    float* Ast = sm;              // [16][132] k-major
    float* Bst = sm + AST_F;      // [16][132]
    float* Cs  = sm;              // [128][132] overlay

    int b = blockIdx.y;
    int p = blockIdx.x;
    int I = 0;
    while (p >= NT - I) { p -= NT - I; I++; }
    int J = I + p;

    int tid = threadIdx.x;
    int tx = tid & 15, ty = tid >> 4;
    const float* Abase = g_normed + ((size_t)b * NN + (size_t)I * TILE) * DD;
    const float* Bbase = g_normed + ((size_t)b * NN + (size_t)J * TILE) * DD;

    int r0 = tid >> 2, q0 = tid & 3;
    int r1 = r0 + 64;

    unsigned long long acc[32];   // [i<8 rows][jp<4 col-pairs]
    #pragma unroll
    for (int i = 0; i < 32; i++) acc[i] = 0ull;

    float4 vA0 = *(const float4*)(Abase + r0 * DD + q0 * 4);
    float4 vA1 = *(const float4*)(Abase + r1 * DD + q0 * 4);
    float4 vB0 = *(const float4*)(Bbase + r0 * DD + q0 * 4);
    float4 vB1 = *(const float4*)(Bbase + r1 * DD + q0 * 4);

    for (int c = 0; c < NCH; c++) {
        {
            float a0[4] = {vA0.x, vA0.y, vA0.z, vA0.w};
            float a1[4] = {vA1.x, vA1.y, vA1.z, vA1.w};
            float b0[4] = {vB0.x, vB0.y, vB0.z, vB0.w};
            float b1[4] = {vB1.x, vB1.y, vB1.z, vB1.w};
            #pragma unroll
            for (int e = 0; e < 4; e++) {
                int k = q0 * 4 + e;
                Ast[k * PADM + r0] = a0[e];
                Ast[k * PADM + r1] = a1[e];
                Bst[k * PADM + r0] = b0[e];
                Bst[k * PADM + r1] = b1[e];
            }
        }
        __syncthreads();

        if (c + 1 < NCH) {
            int k0 = (c + 1) * KC;
            vA0 = *(const float4*)(Abase + r0 * DD + k0 + q0 * 4);
            vA1 = *(const float4*)(Abase + r1 * DD + k0 + q0 * 4);
            vB0 = *(const float4*)(Bbase + r0 * DD + k0 + q0 * 4);
            vB1 = *(const float4*)(Bbase + r1 * DD + k0 + q0 * 4);
        }

        #pragma unroll
        for (int k = 0; k < KC; k++) {
            float4 a0 = *(const float4*)&Ast[k * PADM + ty * 4];
            float4 a1 = *(const float4*)&Ast[k * PADM + 64 + ty * 4];
            float4 b0 = *(const float4*)&Bst[k * PADM + tx * 4];
            float4 b1 = *(const float4*)&Bst[k * PADM + 64 + tx * 4];
            unsigned long long bp[4];
            bp[0] = pk2(b0.x, b0.y); bp[1] = pk2(b0.z, b0.w);
            bp[2] = pk2(b1.x, b1.y); bp[3] = pk2(b1.z, b1.w);
            float av[8] = {a0.x, a0.y, a0.z, a0.w, a1.x, a1.y, a1.z, a1.w};
            #pragma unroll
            for (int i = 0; i < 8; i++) {
                unsigned long long ad = pk2(av[i], av[i]);
                FMA2(acc[i * 4 + 0], ad, bp[0]);
                FMA2(acc[i * 4 + 1], ad, bp[1]);
                FMA2(acc[i * 4 + 2], ad, bp[2]);
                FMA2(acc[i * 4 + 3], ad, bp[3]);
            }
        }
        __syncthreads();
    }

    // write scores: rows ty*4+i (+64), col pairs tx*4 / 64+tx*4
    #pragma unroll
    for (int i = 0; i < 8; i++) {
        int row = (i < 4) ? (ty * 4 + i) : (64 + ty * 4 + i - 4);
        #pragma unroll
        for (int jp = 0; jp < 4; jp++) {
            int col = (jp < 2) ? (tx * 4 + jp * 2) : (64 + tx * 4 + (jp - 2) * 2);
            float lo, hi;
            upk2(lo, hi, acc[i * 4 + jp]);
            *(float2*)&Cs[row * PADC + col] = make_float2(lo, hi);
        }
    }
    __syncthreads();

    if (tid < 128) {
        size_t grow = (size_t)b * NN + (size_t)I * TILE + tid;
        scan_topk2(Cs + tid * PADC, 1, J * TILE, tid, sm,
                   g_pval + (grow * NT + J) * K_TOP,
                   g_pidx + (grow * NT + J) * K_TOP);
    } else if (I != J) {
        int cc = tid - 128;
        size_t grow = (size_t)b * NN + (size_t)J * TILE + cc;
        scan_topk2(Cs + cc, PADC, I * TILE, tid, sm,
                   g_pval + (grow * NT + I) * K_TOP,
                   g_pidx + (grow * NT + I) * K_TOP);
    }
}

// ---------------------------------------------------------------------------
// merge: one thread per row. V8 via sorting network over 128 candidates,
// then select >V8 indices + first equals ascending (exact top-k index SET —
// output order is irrelevant for the scatter).
// ---------------------------------------------------------------------------
__global__ void merge_scatter_kernel(float* __restrict__ out) {
    int row = blockIdx.x * blockDim.x + threadIdx.x;
    if (row >= BB * NN) return;
    int b = row >> 11, n = row & (NN - 1);
    const float* pv = g_pval + (size_t)row * 128;
    const int*   pi = g_pidx + (size_t)row * 128;

    float s[8];
    #pragma unroll
    for (int k = 0; k < 8; k++) s[k] = NEG_INF;
    for (int g = 0; g < 16; g++) {
        float4 v0 = *(const float4*)&pv[8 * g];
        float4 v1 = *(const float4*)&pv[8 * g + 4];
        float e[8] = {v0.x, v0.y, v0.z, v0.w, v1.x, v1.y, v1.z, v1.w};
        SORT8_MERGE(e, s)
    }
    float V8 = s[0];    // global exact 8th-largest of the row

    int gidx[8], eidx[8];
    int gc = 0, ec = 0;
    for (int k = 0; k < 128; k++) {
        float v = pv[k];
        if (v > V8) {                    // at most 7
            gidx[gc & 7] = pi[k]; gc++;
        } else if (v == V8 && ec < 8) {  // ascending index order by construction
            eidx[ec] = pi[k]; ec++;
        }
    }

    float* base = out + (size_t)b * NN * NN;
    #pragma unroll
    for (int q = 0; q < 8; q++) {
        int e = q - gc; if (e < 0) e = 0; if (e > 7) e = 7;
        int idx = (q < gc) ? gidx[q] : eidx[e];
        base[(size_t)n * NN + idx] = 1.0f;
        base[(size_t)idx * NN + n] = 1.0f;
    }
    base[(size_t)n * NN + n] = 1.0f;
}

// ---------------------------------------------------------------------------
extern "C" void kernel_launch(void* const* d_in, const int* in_sizes, int n_in,
                              void* d_out, int out_size) {
    const float* x = (const float*)d_in[0];
    float* out = (float*)d_out;

    int smem = SM_TOT * 4;   // 90112
    cudaFuncSetAttribute(gemm_topk_kernel,
                         cudaFuncAttributeMaxDynamicSharedMemorySize, smem);

    dummy_kernel<<<1, 32>>>();
    normzero_kernel<<<2048, 256>>>(x, (float4*)out, out_size / 4);
    dummy_kernel<<<1, 32>>>();
    gemm_topk_kernel<<<dim3(NT * (NT + 1) / 2, BB), 256, smem>>>();
    merge_scatter_kernel<<<64, 256>>>(out);
}

// round 15
// speedup vs baseline: 1.1860x; 1.1860x over previous
#include <cuda_runtime.h>
#include <cstdint>

#define BB 8
#define NN 2048
#define DD 128
#define K_TOP 8
#define TILE 128
#define NT 16
#define PADC 132
#define NEG_INF (-3.402823466e38f)

#define KC 16
#define NCH 8
#define PADM 132
#define AST_F (KC * PADM)     // 2112 floats per staged tile

// smem word offsets (floats)
#define CS_F   (TILE * PADC)          // 16896
#define SGV_O  CS_F
#define SGI_O  (CS_F + 7 * 256)
#define SEI_O  (CS_F + 14 * 256)
#define SM_TOT (CS_F + 22 * 256)      // 22528 words = 90112 B

__device__ float g_normed[BB * NN * DD];
__device__ float g_pval[BB * NN * NT * K_TOP];
__device__ int   g_pidx[BB * NN * NT * K_TOP];

#define FMA2(d, a, b) asm("fma.rn.f32x2 %0, %1, %2, %0;" : "+l"(d) : "l"(a), "l"(b))
__device__ __forceinline__ unsigned long long pk2(float lo, float hi) {
    unsigned long long d;
    asm("mov.b64 %0, {%1, %2};" : "=l"(d) : "f"(lo), "f"(hi));
    return d;
}
__device__ __forceinline__ void upk2(float& lo, float& hi, unsigned long long v) {
    asm("mov.b64 {%0, %1}, %2;" : "=f"(lo), "=f"(hi) : "l"(v));
}
#define CASF(a, b) { float _t = fminf(a, b); b = fmaxf(a, b); a = _t; }

// sort 8 ascending (Batcher, 19 CAS) then merge into running sorted s[8]
#define SORT8_MERGE(e, s)                                                   \
    CASF(e[0], e[1]) CASF(e[2], e[3]) CASF(e[4], e[5]) CASF(e[6], e[7])     \
    CASF(e[0], e[2]) CASF(e[1], e[3]) CASF(e[4], e[6]) CASF(e[5], e[7])     \
    CASF(e[1], e[2]) CASF(e[5], e[6])                                       \
    CASF(e[0], e[4]) CASF(e[1], e[5]) CASF(e[2], e[6]) CASF(e[3], e[7])     \
    CASF(e[2], e[4]) CASF(e[3], e[5])                                       \
    CASF(e[1], e[2]) CASF(e[3], e[4]) CASF(e[5], e[6])                      \
    _Pragma("unroll")                                                       \
    for (int _i = 0; _i < 8; _i++) s[_i] = fmaxf(s[_i], e[7 - _i]);         \
    CASF(s[0], s[4]) CASF(s[1], s[5]) CASF(s[2], s[6]) CASF(s[3], s[7])     \
    CASF(s[0], s[2]) CASF(s[1], s[3]) CASF(s[4], s[6]) CASF(s[5], s[7])     \
    CASF(s[0], s[1]) CASF(s[2], s[3]) CASF(s[4], s[5]) CASF(s[6], s[7])

// ---------------------------------------------------------------------------
__global__ void dummy_kernel() {}   // keeps gemm in ncu's profiled slot

__global__ void normalize_kernel(const float* __restrict__ x) {
    int row  = (blockIdx.x * blockDim.x + threadIdx.x) >> 5;
    int lane = threadIdx.x & 31;
    if (row >= BB * NN) return;
    float4 v = ((const float4*)(x + (size_t)row * DD))[lane];
    float s = v.x * v.x + v.y * v.y + v.z * v.z + v.w * v.w;
    #pragma unroll
    for (int o = 16; o; o >>= 1) s += __shfl_xor_sync(0xffffffffu, s, o);
    float nrm = fmaxf(sqrtf(s), 1e-12f);
    float4 ov = make_float4(v.x / nrm, v.y / nrm, v.z / nrm, v.w / nrm);
    ((float4*)(g_normed + (size_t)row * DD))[lane] = ov;
}

__global__ void zero_kernel(float4* __restrict__ out, int n4) {
    int i = blockIdx.x * blockDim.x + threadIdx.x;
    int st = gridDim.x * blockDim.x;
    float4 z = make_float4(0.f, 0.f, 0.f, 0.f);
    for (; i < n4; i += st) out[i] = z;
}

// ---------------------------------------------------------------------------
// two-pass exact top-8 for the gemm tile scan (R14, measured)
// ---------------------------------------------------------------------------
__device__ __forceinline__ void scan_topk2(const float* __restrict__ base, int stp,
                                           int ib, int tid, float* sm,
                                           float* __restrict__ pv, int* __restrict__ pi) {
    float s[8];
    #pragma unroll
    for (int k = 0; k < 8; k++) s[k] = NEG_INF;

    for (int g = 0; g < 16; g++) {
        float e[8];
        if (stp == 1) {
            float4 v0 = *(const float4*)&base[8 * g];
            float4 v1 = *(const float4*)&base[8 * g + 4];
            e[0] = v0.x; e[1] = v0.y; e[2] = v0.z; e[3] = v0.w;
            e[4] = v1.x; e[5] = v1.y; e[6] = v1.z; e[7] = v1.w;
        } else {
            #pragma unroll
            for (int j = 0; j < 8; j++) e[j] = base[(8 * g + j) * stp];
        }
        SORT8_MERGE(e, s)
    }
    float V8 = s[0];   // exact 8th-largest of the 128

    float* sgv = sm + SGV_O;
    int*   sgi = (int*)(sm + SGI_O);
    int*   sei = (int*)(sm + SEI_O);
    int gc = 0, ec = 0;
    for (int k = 0; k < TILE; k++) {
        float v = base[k * stp];
        if (v > V8) {
            sgv[gc * 256 + tid] = v;
            sgi[gc * 256 + tid] = ib + k;
            gc++;
        } else if (v == V8 && ec < 8) {
            sei[ec * 256 + tid] = ib + k;
            ec++;
        }
    }
    #pragma unroll
    for (int q = 0; q < 8; q++) {
        bool g = q < gc;
        int ei = q - gc; if (ei < 0) ei = 0;
        pv[q] = g ? sgv[q * 256 + tid] : V8;
        pi[q] = g ? sgi[q * 256 + tid] : sei[ei * 256 + tid];
    }
}

// ---------------------------------------------------------------------------
// symmetric 128x128 tile: R9 f32x2 GEMM core + network two-pass top-8
// (R14 verbatim, measured 151.7us)
// ---------------------------------------------------------------------------
__global__ void __launch_bounds__(256, 2) gemm_topk_kernel() {
    extern __shared__ float sm[];
    float* Ast = sm;              // [16][132] k-major
    float* Bst = sm + AST_F;      // [16][132]
    float* Cs  = sm;              // [128][132] overlay

    int b = blockIdx.y;
    int p = blockIdx.x;
    int I = 0;
    while (p >= NT - I) { p -= NT - I; I++; }
    int J = I + p;

    int tid = threadIdx.x;
    int tx = tid & 15, ty = tid >> 4;
    const float* Abase = g_normed + ((size_t)b * NN + (size_t)I * TILE) * DD;
    const float* Bbase = g_normed + ((size_t)b * NN + (size_t)J * TILE) * DD;

    int r0 = tid >> 2, q0 = tid & 3;
    int r1 = r0 + 64;

    unsigned long long acc[32];   // [i<8 rows][jp<4 col-pairs]
    #pragma unroll
    for (int i = 0; i < 32; i++) acc[i] = 0ull;

    float4 vA0 = *(const float4*)(Abase + r0 * DD + q0 * 4);
    float4 vA1 = *(const float4*)(Abase + r1 * DD + q0 * 4);
    float4 vB0 = *(const float4*)(Bbase + r0 * DD + q0 * 4);
    float4 vB1 = *(const float4*)(Bbase + r1 * DD + q0 * 4);

    for (int c = 0; c < NCH; c++) {
        {
            float a0[4] = {vA0.x, vA0.y, vA0.z, vA0.w};
            float a1[4] = {vA1.x, vA1.y, vA1.z, vA1.w};
            float b0[4] = {vB0.x, vB0.y, vB0.z, vB0.w};
            float b1[4] = {vB1.x, vB1.y, vB1.z, vB1.w};
            #pragma unroll
            for (int e = 0; e < 4; e++) {
                int k = q0 * 4 + e;
                Ast[k * PADM + r0] = a0[e];
                Ast[k * PADM + r1] = a1[e];
                Bst[k * PADM + r0] = b0[e];
                Bst[k * PADM + r1] = b1[e];
            }
        }
        __syncthreads();

        if (c + 1 < NCH) {
            int k0 = (c + 1) * KC;
            vA0 = *(const float4*)(Abase + r0 * DD + k0 + q0 * 4);
            vA1 = *(const float4*)(Abase + r1 * DD + k0 + q0 * 4);
            vB0 = *(const float4*)(Bbase + r0 * DD + k0 + q0 * 4);
            vB1 = *(const float4*)(Bbase + r1 * DD + k0 + q0 * 4);
        }

        #pragma unroll
        for (int k = 0; k < KC; k++) {
            float4 a0 = *(const float4*)&Ast[k * PADM + ty * 4];
            float4 a1 = *(const float4*)&Ast[k * PADM + 64 + ty * 4];
            float4 b0 = *(const float4*)&Bst[k * PADM + tx * 4];
            float4 b1 = *(const float4*)&Bst[k * PADM + 64 + tx * 4];
            unsigned long long bp[4];
            bp[0] = pk2(b0.x, b0.y); bp[1] = pk2(b0.z, b0.w);
            bp[2] = pk2(b1.x, b1.y); bp[3] = pk2(b1.z, b1.w);
            float av[8] = {a0.x, a0.y, a0.z, a0.w, a1.x, a1.y, a1.z, a1.w};
            #pragma unroll
            for (int i = 0; i < 8; i++) {
                unsigned long long ad = pk2(av[i], av[i]);
                FMA2(acc[i * 4 + 0], ad, bp[0]);
                FMA2(acc[i * 4 + 1], ad, bp[1]);
                FMA2(acc[i * 4 + 2], ad, bp[2]);
                FMA2(acc[i * 4 + 3], ad, bp[3]);
            }
        }
        __syncthreads();
    }

    // write scores: rows ty*4+i (+64), col pairs tx*4 / 64+tx*4
    #pragma unroll
    for (int i = 0; i < 8; i++) {
        int row = (i < 4) ? (ty * 4 + i) : (64 + ty * 4 + i - 4);
        #pragma unroll
        for (int jp = 0; jp < 4; jp++) {
            int col = (jp < 2) ? (tx * 4 + jp * 2) : (64 + tx * 4 + (jp - 2) * 2);
            float lo, hi;
            upk2(lo, hi, acc[i * 4 + jp]);
            *(float2*)&Cs[row * PADC + col] = make_float2(lo, hi);
        }
    }
    __syncthreads();

    if (tid < 128) {
        size_t grow = (size_t)b * NN + (size_t)I * TILE + tid;
        scan_topk2(Cs + tid * PADC, 1, J * TILE, tid, sm,
                   g_pval + (grow * NT + J) * K_TOP,
                   g_pidx + (grow * NT + J) * K_TOP);
    } else if (I != J) {
        int cc = tid - 128;
        size_t grow = (size_t)b * NN + (size_t)J * TILE + cc;
        scan_topk2(Cs + cc, PADC, I * TILE, tid, sm,
                   g_pval + (grow * NT + I) * K_TOP,
                   g_pidx + (grow * NT + I) * K_TOP);
    }
}

// ---------------------------------------------------------------------------
// merge: R9 warp-per-row version (measured ~18.4us across five rounds)
// ---------------------------------------------------------------------------
__global__ void merge_scatter_kernel(float* __restrict__ out) {
    int gw   = (blockIdx.x * blockDim.x + threadIdx.x) >> 5;
    int lane = threadIdx.x & 31;
    if (gw >= BB * NN) return;
    int b = gw / NN, n = gw % NN;
    const float* pv = g_pval + (size_t)gw * NT * K_TOP;
    const int*   pi = g_pidx + (size_t)gw * NT * K_TOP;
    float v[4]; int id[4];
    #pragma unroll
    for (int q = 0; q < 4; q++) {
        v[q]  = pv[lane + 32 * q];
        id[q] = pi[lane + 32 * q];
    }
    float* base = out + (size_t)b * NN * NN;
    #pragma unroll
    for (int t = 0; t < K_TOP; t++) {
        float bv = v[0]; int bi = id[0];
        #pragma unroll
        for (int q = 1; q < 4; q++)
            if (v[q] > bv || (v[q] == bv && id[q] < bi)) { bv = v[q]; bi = id[q]; }
        #pragma unroll
        for (int off = 16; off; off >>= 1) {
            float ov = __shfl_xor_sync(0xffffffffu, bv, off);
            int   oi = __shfl_xor_sync(0xffffffffu, bi, off);
            if (ov > bv || (ov == bv && oi < bi)) { bv = ov; bi = oi; }
        }
        if (lane == t) {
            base[(size_t)n * NN + bi] = 1.0f;
            base[(size_t)bi * NN + n] = 1.0f;
        }
        #pragma unroll
        for (int q = 0; q < 4; q++)
            if (id[q] == bi) v[q] = NEG_INF;
    }
    if (lane == 8) base[(size_t)n * NN + n] = 1.0f;
}

// ---------------------------------------------------------------------------
extern "C" void kernel_launch(void* const* d_in, const int* in_sizes, int n_in,
                              void* d_out, int out_size) {
    const float* x = (const float*)d_in[0];
    float* out = (float*)d_out;

    int smem = SM_TOT * 4;   // 90112
    cudaFuncSetAttribute(gemm_topk_kernel,
                         cudaFuncAttributeMaxDynamicSharedMemorySize, smem);

    dummy_kernel<<<1, 32>>>();
    normalize_kernel<<<(BB * NN) / 8, 256>>>(x);
    zero_kernel<<<8192, 256>>>((float4*)out, out_size / 4);
    gemm_topk_kernel<<<dim3(NT * (NT + 1) / 2, BB), 256, smem>>>();
    merge_scatter_kernel<<<(BB * NN) / 8, 256>>>(out);
}

// round 16
// speedup vs baseline: 1.2893x; 1.0870x over previous
#include <cuda_runtime.h>
#include <cstdint>

#define BB 8
#define NN 2048
#define DD 128
#define K_TOP 8
#define TILE 128
#define NT 16
#define PADC 132
#define NEG_INF (-3.402823466e38f)

#define KC 16
#define NCH 8
#define PADM 132
#define AST_F (KC * PADM)     // 2112 floats per staged tile

#define SM_TOT (TILE * PADC)  // 16896 words = 67584 B (scores only, no scratch)

__device__ float g_normed[BB * NN * DD];
__device__ float g_pval[BB * NN * NT * K_TOP];
__device__ int   g_pidx[BB * NN * NT * K_TOP];

#define FMA2(d, a, b) asm("fma.rn.f32x2 %0, %1, %2, %0;" : "+l"(d) : "l"(a), "l"(b))
__device__ __forceinline__ unsigned long long pk2(float lo, float hi) {
    unsigned long long d;
    asm("mov.b64 %0, {%1, %2};" : "=l"(d) : "f"(lo), "f"(hi));
    return d;
}
__device__ __forceinline__ void upk2(float& lo, float& hi, unsigned long long v) {
    asm("mov.b64 {%0, %1}, %2;" : "=f"(lo), "=f"(hi) : "l"(v));
}
#define CASF(a, b) { float _t = fminf(a, b); b = fmaxf(a, b); a = _t; }

// sort 8 ascending (Batcher, 19 CAS) then merge into running sorted s[8]
#define SORT8_MERGE(e, s)                                                   \
    CASF(e[0], e[1]) CASF(e[2], e[3]) CASF(e[4], e[5]) CASF(e[6], e[7])     \
    CASF(e[0], e[2]) CASF(e[1], e[3]) CASF(e[4], e[6]) CASF(e[5], e[7])     \
    CASF(e[1], e[2]) CASF(e[5], e[6])                                       \
    CASF(e[0], e[4]) CASF(e[1], e[5]) CASF(e[2], e[6]) CASF(e[3], e[7])     \
    CASF(e[2], e[4]) CASF(e[3], e[5])                                       \
    CASF(e[1], e[2]) CASF(e[3], e[4]) CASF(e[5], e[6])                      \
    _Pragma("unroll")                                                       \
    for (int _i = 0; _i < 8; _i++) s[_i] = fmaxf(s[_i], e[7 - _i]);         \
    CASF(s[0], s[4]) CASF(s[1], s[5]) CASF(s[2], s[6]) CASF(s[3], s[7])     \
    CASF(s[0], s[2]) CASF(s[1], s[3]) CASF(s[4], s[6]) CASF(s[5], s[7])     \
    CASF(s[0], s[1]) CASF(s[2], s[3]) CASF(s[4], s[5]) CASF(s[6], s[7])

// ---------------------------------------------------------------------------
__global__ void dummy_kernel() {}   // keeps gemm in ncu's profiled slot

__global__ void normalize_kernel(const float* __restrict__ x) {
    int row  = (blockIdx.x * blockDim.x + threadIdx.x) >> 5;
    int lane = threadIdx.x & 31;
    if (row >= BB * NN) return;
    float4 v = ((const float4*)(x + (size_t)row * DD))[lane];
    float s = v.x * v.x + v.y * v.y + v.z * v.z + v.w * v.w;
    #pragma unroll
    for (int o = 16; o; o >>= 1) s += __shfl_xor_sync(0xffffffffu, s, o);
    float nrm = fmaxf(sqrtf(s), 1e-12f);
    float4 ov = make_float4(v.x / nrm, v.y / nrm, v.z / nrm, v.w / nrm);
    ((float4*)(g_normed + (size_t)row * DD))[lane] = ov;
}

__global__ void zero_kernel(float4* __restrict__ out, int n4) {
    int i = blockIdx.x * blockDim.x + threadIdx.x;
    int st = gridDim.x * blockDim.x;
    float4 z = make_float4(0.f, 0.f, 0.f, 0.f);
    for (; i < n4; i += st) out[i] = z;
}

// ---------------------------------------------------------------------------
// two-pass exact top-8, scratch-free:
// pass 1: sorting-network top-8 values -> V8 (exact 8th largest) and
//         gcnt = exact count of strict-greaters (from sorted s registers)
// pass 2: direct global emit — greaters at slots 0..gcnt-1 (ascending k),
//         equals (==V8) at slots gcnt..7 (first 8-gcnt, ascending k)
//         == exact lax.top_k (value desc, index asc) candidate set.
// ---------------------------------------------------------------------------
__device__ __forceinline__ void scan_topk2(const float* __restrict__ base, int stp,
                                           int ib,
                                           float* __restrict__ pv, int* __restrict__ pi) {
    float s[8];
    #pragma unroll
    for (int k = 0; k < 8; k++) s[k] = NEG_INF;

    for (int g = 0; g < 16; g++) {
        float e[8];
        if (stp == 1) {
            float4 v0 = *(const float4*)&base[8 * g];
            float4 v1 = *(const float4*)&base[8 * g + 4];
            e[0] = v0.x; e[1] = v0.y; e[2] = v0.z; e[3] = v0.w;
            e[4] = v1.x; e[5] = v1.y; e[6] = v1.z; e[7] = v1.w;
        } else {
            #pragma unroll
            for (int j = 0; j < 8; j++) e[j] = base[(8 * g + j) * stp];
        }
        SORT8_MERGE(e, s)
    }
    float V8 = s[0];   // exact 8th-largest of the 128

    int gcnt = 0;
    #pragma unroll
    for (int i = 1; i < 8; i++) gcnt += (s[i] > V8) ? 1 : 0;
    int need_eq = 8 - gcnt;

    int gs = 0, es = 0;
    if (stp == 1) {
        for (int g = 0; g < 32; g++) {
            float4 v4 = *(const float4*)&base[4 * g];
            float e[4] = {v4.x, v4.y, v4.z, v4.w};
            #pragma unroll
            for (int j = 0; j < 4; j++) {
                float v = e[j];
                if (v > V8) {
                    pv[gs] = v; pi[gs] = ib + 4 * g + j; gs++;
                } else if (v == V8 && es < need_eq) {
                    int slot = gcnt + es;
                    pv[slot] = V8; pi[slot] = ib + 4 * g + j; es++;
                }
            }
        }
    } else {
        for (int k = 0; k < TILE; k++) {
            float v = base[k * stp];
            if (v > V8) {
                pv[gs] = v; pi[gs] = ib + k; gs++;
            } else if (v == V8 && es < need_eq) {
                int slot = gcnt + es;
                pv[slot] = V8; pi[slot] = ib + k; es++;
            }
        }
    }
}

// ---------------------------------------------------------------------------
// symmetric 128x128 tile: R9 f32x2 GEMM core + scratch-free network top-8
// grid (136, 8), 256 threads, 2 CTAs/SM, dyn smem = 67584 B
// ---------------------------------------------------------------------------
__global__ void __launch_bounds__(256, 2) gemm_topk_kernel() {
    extern __shared__ float sm[];
    float* Ast = sm;              // [16][132] k-major
    float* Bst = sm + AST_F;      // [16][132]
    float* Cs  = sm;              // [128][132] overlay

    int b = blockIdx.y;
    int p = blockIdx.x;
    int I = 0;
    while (p >= NT - I) { p -= NT - I; I++; }
    int J = I + p;

    int tid = threadIdx.x;
    int tx = tid & 15, ty = tid >> 4;
    const float* Abase = g_normed + ((size_t)b * NN + (size_t)I * TILE) * DD;
    const float* Bbase = g_normed + ((size_t)b * NN + (size_t)J * TILE) * DD;

    int r0 = tid >> 2, q0 = tid & 3;
    int r1 = r0 + 64;

    unsigned long long acc[32];   // [i<8 rows][jp<4 col-pairs]
    #pragma unroll
    for (int i = 0; i < 32; i++) acc[i] = 0ull;

    float4 vA0 = *(const float4*)(Abase + r0 * DD + q0 * 4);
    float4 vA1 = *(const float4*)(Abase + r1 * DD + q0 * 4);
    float4 vB0 = *(const float4*)(Bbase + r0 * DD + q0 * 4);
    float4 vB1 = *(const float4*)(Bbase + r1 * DD + q0 * 4);

    for (int c = 0; c < NCH; c++) {
        {
            float a0[4] = {vA0.x, vA0.y, vA0.z, vA0.w};
            float a1[4] = {vA1.x, vA1.y, vA1.z, vA1.w};
            float b0[4] = {vB0.x, vB0.y, vB0.z, vB0.w};
            float b1[4] = {vB1.x, vB1.y, vB1.z, vB1.w};
            #pragma unroll
            for (int e = 0; e < 4; e++) {
                int k = q0 * 4 + e;
                Ast[k * PADM + r0] = a0[e];
                Ast[k * PADM + r1] = a1[e];
                Bst[k * PADM + r0] = b0[e];
                Bst[k * PADM + r1] = b1[e];
            }
        }
        __syncthreads();

        if (c + 1 < NCH) {
            int k0 = (c + 1) * KC;
            vA0 = *(const float4*)(Abase + r0 * DD + k0 + q0 * 4);
            vA1 = *(const float4*)(Abase + r1 * DD + k0 + q0 * 4);
            vB0 = *(const float4*)(Bbase + r0 * DD + k0 + q0 * 4);
            vB1 = *(const float4*)(Bbase + r1 * DD + k0 + q0 * 4);
        }

        #pragma unroll
        for (int k = 0; k < KC; k++) {
            float4 a0 = *(const float4*)&Ast[k * PADM + ty * 4];
            float4 a1 = *(const float4*)&Ast[k * PADM + 64 + ty * 4];
            float4 b0 = *(const float4*)&Bst[k * PADM + tx * 4];
            float4 b1 = *(const float4*)&Bst[k * PADM + 64 + tx * 4];
            unsigned long long bp[4];
            bp[0] = pk2(b0.x, b0.y); bp[1] = pk2(b0.z, b0.w);
            bp[2] = pk2(b1.x, b1.y); bp[3] = pk2(b1.z, b1.w);
            float av[8] = {a0.x, a0.y, a0.z, a0.w, a1.x, a1.y, a1.z, a1.w};
            #pragma unroll
            for (int i = 0; i < 8; i++) {
                unsigned long long ad = pk2(av[i], av[i]);
                FMA2(acc[i * 4 + 0], ad, bp[0]);
                FMA2(acc[i * 4 + 1], ad, bp[1]);
                FMA2(acc[i * 4 + 2], ad, bp[2]);
                FMA2(acc[i * 4 + 3], ad, bp[3]);
            }
        }
        __syncthreads();
    }

    // write scores: rows ty*4+i (+64), col pairs tx*4 / 64+tx*4
    #pragma unroll
    for (int i = 0; i < 8; i++) {
        int row = (i < 4) ? (ty * 4 + i) : (64 + ty * 4 + i - 4);
        #pragma unroll
        for (int jp = 0; jp < 4; jp++) {
            int col = (jp < 2) ? (tx * 4 + jp * 2) : (64 + tx * 4 + (jp - 2) * 2);
            float lo, hi;
            upk2(lo, hi, acc[i * 4 + jp]);
            *(float2*)&Cs[row * PADC + col] = make_float2(lo, hi);
        }
    }
    __syncthreads();

    if (tid < 128) {
        size_t grow = (size_t)b * NN + (size_t)I * TILE + tid;
        scan_topk2(Cs + tid * PADC, 1, J * TILE,
                   g_pval + (grow * NT + J) * K_TOP,
                   g_pidx + (grow * NT + J) * K_TOP);
    } else if (I != J) {
        int cc = tid - 128;
        size_t grow = (size_t)b * NN + (size_t)J * TILE + cc;
        scan_topk2(Cs + cc, PADC, I * TILE,
                   g_pval + (grow * NT + I) * K_TOP,
                   g_pidx + (grow * NT + I) * K_TOP);
    }
}

// ---------------------------------------------------------------------------
// merge: R9 warp-per-row version (measured ~18.4us)
// ---------------------------------------------------------------------------
__global__ void merge_scatter_kernel(float* __restrict__ out) {
    int gw   = (blockIdx.x * blockDim.x + threadIdx.x) >> 5;
    int lane = threadIdx.x & 31;
    if (gw >= BB * NN) return;
    int b = gw / NN, n = gw % NN;
    const float* pv = g_pval + (size_t)gw * NT * K_TOP;
    const int*   pi = g_pidx + (size_t)gw * NT * K_TOP;
    float v[4]; int id[4];
    #pragma unroll
    for (int q = 0; q < 4; q++) {
        v[q]  = pv[lane + 32 * q];
        id[q] = pi[lane + 32 * q];
    }
    float* base = out + (size_t)b * NN * NN;
    #pragma unroll
    for (int t = 0; t < K_TOP; t++) {
        float bv = v[0]; int bi = id[0];
        #pragma unroll
        for (int q = 1; q < 4; q++)
            if (v[q] > bv || (v[q] == bv && id[q] < bi)) { bv = v[q]; bi = id[q]; }
        #pragma unroll
        for (int off = 16; off; off >>= 1) {
            float ov = __shfl_xor_sync(0xffffffffu, bv, off);
            int   oi = __shfl_xor_sync(0xffffffffu, bi, off);
            if (ov > bv || (ov == bv && oi < bi)) { bv = ov; bi = oi; }
        }
        if (lane == t) {
            base[(size_t)n * NN + bi] = 1.0f;
            base[(size_t)bi * NN + n] = 1.0f;
        }
        #pragma unroll
        for (int q = 0; q < 4; q++)
            if (id[q] == bi) v[q] = NEG_INF;
    }
    if (lane == 8) base[(size_t)n * NN + n] = 1.0f;
}

// ---------------------------------------------------------------------------
extern "C" void kernel_launch(void* const* d_in, const int* in_sizes, int n_in,
                              void* d_out, int out_size) {
    const float* x = (const float*)d_in[0];
    float* out = (float*)d_out;

    int smem = SM_TOT * 4;   // 67584
    cudaFuncSetAttribute(gemm_topk_kernel,
                         cudaFuncAttributeMaxDynamicSharedMemorySize, smem);

    dummy_kernel<<<1, 32>>>();
    normalize_kernel<<<(BB * NN) / 8, 256>>>(x);
    zero_kernel<<<8192, 256>>>((float4*)out, out_size / 4);
    gemm_topk_kernel<<<dim3(NT * (NT + 1) / 2, BB), 256, smem>>>();
    merge_scatter_kernel<<<(BB * NN) / 8, 256>>>(out);
}